// round 1
// baseline (speedup 1.0000x reference)
#include <cuda_runtime.h>
#include <math.h>

// GraphTemporalRefiner: only a[:, -1, :] feeds the output head, so attention
// collapses to per-(batch,head) GEMVs over xg = conv7(x).
//
// xg = adj_conv(x)                       (B,T,64)
// q_b = Wq (theta xg_last + theta_b) + bq
// scores[b,n,t] = w[b,n] . xg[b,t]  (+const, dropped)  with w = theta^T Wk_n^T q_n / sqrt(HD)
// u[b,n] = sum_t softmax_t * xg[b,t]
// o[b, n*32+j] = Wv[row] . (theta u + theta_b) + bv
// a = out_proj(o); LN; gelu-MLP -> out (B,2)

namespace {
constexpr int Bn  = 32;
constexpr int Tn  = 1024;
constexpr int Dn  = 64;    // D_IN
constexpr int Hn  = 128;
constexpr int NHn = 4;
constexpr int HDn = 32;
}

__device__ __align__(16) float g_xg[Bn * Tn * Dn];   // 8 MB scratch

// ---------------------------------------------------------------------------
// K1: banded conv along T (radius 3, weights 1/(1+|d|), row-normalized)
// ---------------------------------------------------------------------------
__global__ void conv_kernel(const float* __restrict__ x) {
    int idx = blockIdx.x * 256 + threadIdx.x;        // over B*T*D = 2M, exact grid
    int d = idx & (Dn - 1);
    int t = (idx >> 6) & (Tn - 1);
    int b = idx >> 16;                               // T*D = 65536
    float sum = 0.f, wsum = 0.f;
#pragma unroll
    for (int dd = -3; dd <= 3; dd++) {
        int tt = t + dd;
        if (tt >= 0 && tt < Tn) {
            float wv = 1.0f / (1.0f + (float)(dd < 0 ? -dd : dd));
            wsum += wv;
            sum += wv * __ldg(&x[(b * Tn + tt) * Dn + d]);
        }
    }
    g_xg[idx] = sum / wsum;
}

// ---------------------------------------------------------------------------
// K2: one block per batch. Prologue GEMVs, scores, softmax, weighted
// reduction, then the whole tail (out_proj, LN, gelu MLP, final proj).
// ---------------------------------------------------------------------------
__global__ void __launch_bounds__(256) attn_tail_kernel(
    const float* __restrict__ theta_w,   // (H, D)
    const float* __restrict__ theta_b,   // (H)
    const float* __restrict__ in_proj_w, // (3H, H)
    const float* __restrict__ in_proj_b, // (3H)
    const float* __restrict__ out_proj_w,// (H, H)
    const float* __restrict__ out_proj_b,// (H)
    const float* __restrict__ ln_g,
    const float* __restrict__ ln_b,
    const float* __restrict__ w1,        // (H, H)
    const float* __restrict__ b1,
    const float* __restrict__ w2,        // (2, H)
    const float* __restrict__ b2,
    float* __restrict__ out)             // (B, 2)
{
    const int b   = blockIdx.x;
    const int tid = threadIdx.x;

    __shared__ float sc[NHn][Tn];        // scores -> exp weights (16 KB)
    __shared__ float tile[64][65];       // xg staging, padded (16.25 KB)
    __shared__ float s_glast[Hn];
    __shared__ float s_q[Hn];
    __shared__ float s_p[NHn][Hn];
    __shared__ float s_w[NHn][Dn];
    __shared__ float s_red[8][NHn];
    __shared__ float s_stat[2 * NHn];    // [0..3]=max, [4..7]=sum
    __shared__ float s_upart[4][NHn][Dn];
    __shared__ float s_u[NHn][Dn];
    __shared__ float s_gu[NHn][Hn];
    __shared__ float s_o[Hn];
    __shared__ float s_a[Hn];
    __shared__ float s_ln[Hn];
    __shared__ float s_hid[Hn];
    __shared__ float s_mv[2];            // mean, var

    const float* xb = &g_xg[b * Tn * Dn];

    // ---- prologue: g_last, q, p, w -------------------------------------
    if (tid < Hn) {
        float acc = theta_b[tid];
        const float* xl = &xb[(Tn - 1) * Dn];
#pragma unroll 8
        for (int d = 0; d < Dn; d++) acc += theta_w[tid * Dn + d] * xl[d];
        s_glast[tid] = acc;
    }
    __syncthreads();
    if (tid < Hn) {
        float acc = in_proj_b[tid];                  // Wq rows = 0..H-1
#pragma unroll 8
        for (int c = 0; c < Hn; c++) acc += in_proj_w[tid * Hn + c] * s_glast[c];
        s_q[tid] = acc;
    }
    __syncthreads();
    for (int e = tid; e < NHn * Hn; e += 256) {      // p[n][c] = sum_j q[n,j] Wk[n*32+j, c]
        int n = e >> 7, c = e & (Hn - 1);
        float acc = 0.f;
#pragma unroll 8
        for (int j = 0; j < HDn; j++)
            acc += s_q[n * HDn + j] * in_proj_w[(Hn + n * HDn + j) * Hn + c];
        s_p[n][c] = acc;
    }
    __syncthreads();
    {                                                // w[n][d] = sum_c p[n][c] theta[c][d]
        int n = tid >> 6, d = tid & (Dn - 1);
        float acc = 0.f;
#pragma unroll 8
        for (int c = 0; c < Hn; c++) acc += s_p[n][c] * theta_w[c * Dn + d];
        s_w[n][d] = acc * 0.17677669529663687f;      // 1/sqrt(HD)
    }
    __syncthreads();

    // ---- pass A: scores via smem-tiled GEMV -----------------------------
    for (int chunk = 0; chunk < Tn / 64; chunk++) {
        const float4* src = (const float4*)&xb[(chunk * 64) * Dn];
        for (int i = tid; i < 64 * 16; i += 256) {   // 64 rows x 16 float4
            int row = i >> 4, c4 = i & 15;
            float4 v = src[row * 16 + c4];
            tile[row][c4 * 4 + 0] = v.x;
            tile[row][c4 * 4 + 1] = v.y;
            tile[row][c4 * 4 + 2] = v.z;
            tile[row][c4 * 4 + 3] = v.w;
        }
        __syncthreads();
        int tl = tid & 63, n = tid >> 6;
        float acc = 0.f;
#pragma unroll 8
        for (int d = 0; d < Dn; d++) acc += s_w[n][d] * tile[tl][d];
        sc[n][chunk * 64 + tl] = acc;
        __syncthreads();
    }

    // ---- softmax: max ----------------------------------------------------
    float lv[NHn];
#pragma unroll
    for (int n = 0; n < NHn; n++) lv[n] = -1e30f;
    for (int t = tid; t < Tn; t += 256)
#pragma unroll
        for (int n = 0; n < NHn; n++) lv[n] = fmaxf(lv[n], sc[n][t]);
#pragma unroll
    for (int off = 16; off; off >>= 1)
#pragma unroll
        for (int n = 0; n < NHn; n++)
            lv[n] = fmaxf(lv[n], __shfl_xor_sync(0xFFFFFFFFu, lv[n], off));
    if ((tid & 31) == 0)
#pragma unroll
        for (int n = 0; n < NHn; n++) s_red[tid >> 5][n] = lv[n];
    __syncthreads();
    if (tid < NHn) {
        float m = s_red[0][tid];
#pragma unroll
        for (int wpr = 1; wpr < 8; wpr++) m = fmaxf(m, s_red[wpr][tid]);
        s_stat[tid] = m;
    }
    __syncthreads();

    // ---- softmax: exp + sum ----------------------------------------------
#pragma unroll
    for (int n = 0; n < NHn; n++) lv[n] = 0.f;
    for (int t = tid; t < Tn; t += 256)
#pragma unroll
        for (int n = 0; n < NHn; n++) {
            float e = expf(sc[n][t] - s_stat[n]);
            sc[n][t] = e;
            lv[n] += e;
        }
#pragma unroll
    for (int off = 16; off; off >>= 1)
#pragma unroll
        for (int n = 0; n < NHn; n++) lv[n] += __shfl_xor_sync(0xFFFFFFFFu, lv[n], off);
    if ((tid & 31) == 0)
#pragma unroll
        for (int n = 0; n < NHn; n++) s_red[tid >> 5][n] = lv[n];
    __syncthreads();
    if (tid < NHn) {
        float s = 0.f;
#pragma unroll
        for (int wpr = 0; wpr < 8; wpr++) s += s_red[wpr][tid];
        s_stat[NHn + tid] = s;
    }
    __syncthreads();

    // ---- pass D: u[n] = sum_t attn[n,t] * xg[t] --------------------------
    {
        int g = tid >> 6, d = tid & (Dn - 1);
        float acc[NHn] = {0.f, 0.f, 0.f, 0.f};
        for (int t = g; t < Tn; t += 4) {
            float v = xb[t * Dn + d];
#pragma unroll
            for (int n = 0; n < NHn; n++) acc[n] += sc[n][t] * v;
        }
#pragma unroll
        for (int n = 0; n < NHn; n++) s_upart[g][n][d] = acc[n];
    }
    __syncthreads();
    {
        int n = tid >> 6, d = tid & (Dn - 1);
        float u = (s_upart[0][n][d] + s_upart[1][n][d] +
                   s_upart[2][n][d] + s_upart[3][n][d]) / s_stat[NHn + n];
        s_u[n][d] = u;
    }
    __syncthreads();

    // ---- tail: gu, o, out_proj -------------------------------------------
    for (int e = tid; e < NHn * Hn; e += 256) {      // gu[n][c] = theta u + theta_b
        int n = e >> 7, c = e & (Hn - 1);
        float acc = theta_b[c];
#pragma unroll 8
        for (int d = 0; d < Dn; d++) acc += theta_w[c * Dn + d] * s_u[n][d];
        s_gu[n][c] = acc;
    }
    __syncthreads();
    if (tid < Hn) {                                  // o[h] = Wv[2H+h] . gu[h/32]
        int n = tid >> 5;
        float acc = in_proj_b[2 * Hn + tid];
#pragma unroll 8
        for (int c = 0; c < Hn; c++)
            acc += in_proj_w[(2 * Hn + tid) * Hn + c] * s_gu[n][c];
        s_o[tid] = acc;
    }
    __syncthreads();
    if (tid < Hn) {                                  // a = out_proj(o)
        float acc = out_proj_b[tid];
#pragma unroll 8
        for (int h = 0; h < Hn; h++) acc += out_proj_w[tid * Hn + h] * s_o[h];
        s_a[tid] = acc;
    }
    __syncthreads();

    // ---- LayerNorm over 128 -----------------------------------------------
    if (tid < 32) {
        float s = s_a[tid] + s_a[tid + 32] + s_a[tid + 64] + s_a[tid + 96];
#pragma unroll
        for (int off = 16; off; off >>= 1) s += __shfl_xor_sync(0xFFFFFFFFu, s, off);
        if (tid == 0) s_mv[0] = s * (1.0f / Hn);
    }
    __syncthreads();
    if (tid < 32) {
        float mu = s_mv[0];
        float s = 0.f;
#pragma unroll
        for (int k = 0; k < 4; k++) {
            float d = s_a[tid + 32 * k] - mu;
            s += d * d;
        }
#pragma unroll
        for (int off = 16; off; off >>= 1) s += __shfl_xor_sync(0xFFFFFFFFu, s, off);
        if (tid == 0) s_mv[1] = s * (1.0f / Hn);
    }
    __syncthreads();
    if (tid < Hn) {
        float inv = rsqrtf(s_mv[1] + 1e-5f);
        s_ln[tid] = (s_a[tid] - s_mv[0]) * inv * ln_g[tid] + ln_b[tid];
    }
    __syncthreads();

    // ---- MLP: gelu(ln @ w1^T + b1) @ w2^T + b2 -----------------------------
    if (tid < Hn) {
        float acc = b1[tid];
#pragma unroll 8
        for (int c = 0; c < Hn; c++) acc += w1[tid * Hn + c] * s_ln[c];
        s_hid[tid] = 0.5f * acc * (1.0f + erff(acc * 0.70710678118654752f));
    }
    __syncthreads();
    if (tid < 2) {
        float acc = b2[tid];
#pragma unroll 8
        for (int h = 0; h < Hn; h++) acc += w2[tid * Hn + h] * s_hid[h];
        out[b * 2 + tid] = acc;
    }
}

// ---------------------------------------------------------------------------
extern "C" void kernel_launch(void* const* d_in, const int* in_sizes, int n_in,
                              void* d_out, int out_size) {
    const float* x          = (const float*)d_in[0];
    const float* theta_w    = (const float*)d_in[1];
    const float* theta_b    = (const float*)d_in[2];
    const float* in_proj_w  = (const float*)d_in[3];
    const float* in_proj_b  = (const float*)d_in[4];
    const float* out_proj_w = (const float*)d_in[5];
    const float* out_proj_b = (const float*)d_in[6];
    const float* lng        = (const float*)d_in[7];
    const float* lnb        = (const float*)d_in[8];
    const float* w1         = (const float*)d_in[9];
    const float* b1         = (const float*)d_in[10];
    const float* w2         = (const float*)d_in[11];
    const float* b2         = (const float*)d_in[12];
    float* out = (float*)d_out;

    conv_kernel<<<(Bn * Tn * Dn) / 256, 256>>>(x);
    attn_tail_kernel<<<Bn, 256>>>(theta_w, theta_b, in_proj_w, in_proj_b,
                                  out_proj_w, out_proj_b, lng, lnb,
                                  w1, b1, w2, b2, out);
}

// round 2
// speedup vs baseline: 1.3138x; 1.3138x over previous
#include <cuda_runtime.h>
#include <math.h>

// GraphTemporalRefiner — split-softmax decomposition.
// Only a[:, -1, :] feeds the output head:
//   xg = conv7(x)                                  (B,T,64)
//   w[b,n,d] = (theta^T Wk_n^T q_{b,n})_d / sqrt(HD),  q from xg[b,T-1]
//   scores[b,n,t] = w[b,n] . xg[b,t]   (const offset cancels in softmax)
//   u[b,n] = softmax-weighted sum_t xg[b,t]
//   o -> out_proj -> LN -> gelu MLP -> out (B,2)
// xg is never materialized in GMEM: K_sc builds each 128-row tile in smem
// straight from x, and the softmax is merged across 8 T-slices (m,l,u).

namespace {
constexpr int Bn  = 32;
constexpr int Tn  = 1024;
constexpr int Dn  = 64;
constexpr int Hn  = 128;
constexpr int NHn = 4;
constexpr int HDn = 32;
constexpr int SL  = 128;        // T-slice per score block
constexpr int NS  = Tn / SL;    // 8 slices
}

__device__ float g_w[Bn * NHn * Dn];            // per-head score weights
__device__ float g_m[Bn * NHn * NS];            // slice max
__device__ float g_l[Bn * NHn * NS];            // slice exp-sum
__device__ float g_u[Bn * NHn * NS * Dn];       // slice weighted xg sums

// ---------------------------------------------------------------------------
// K_pro: per batch — g_last, q, p, w (all from x directly; conv at t=T-1 only)
// ---------------------------------------------------------------------------
__global__ void __launch_bounds__(128) pro_kernel(
    const float* __restrict__ x,
    const float* __restrict__ theta_w,
    const float* __restrict__ theta_b,
    const float* __restrict__ in_proj_w,
    const float* __restrict__ in_proj_b)
{
    const int b = blockIdx.x, tid = threadIdx.x;
    __shared__ float s_xl[Dn];
    __shared__ float s_g[Hn];
    __shared__ float s_q[Hn];
    __shared__ float s_p[NHn][Hn];

    if (tid < Dn) {
        float sum = 0.f, ws = 0.f;
#pragma unroll
        for (int dd = 0; dd < 4; dd++) {        // tt = 1023-dd (forward side OOB)
            float wv = 1.0f / (1.0f + (float)dd);
            ws += wv;
            sum += wv * x[(b * Tn + (Tn - 1 - dd)) * Dn + tid];
        }
        s_xl[tid] = sum / ws;
    }
    __syncthreads();
    {
        float acc = theta_b[tid];
#pragma unroll 8
        for (int d = 0; d < Dn; d++) acc += theta_w[tid * Dn + d] * s_xl[d];
        s_g[tid] = acc;
    }
    __syncthreads();
    {
        float acc = in_proj_b[tid];             // Wq rows 0..H-1
#pragma unroll 8
        for (int c = 0; c < Hn; c++) acc += in_proj_w[tid * Hn + c] * s_g[c];
        s_q[tid] = acc;
    }
    __syncthreads();
    for (int e = tid; e < NHn * Hn; e += 128) { // p[n][c] = q_n . Wk_n[:,c]
        int n = e >> 7, c = e & (Hn - 1);
        float acc = 0.f;
#pragma unroll 8
        for (int j = 0; j < HDn; j++)
            acc += s_q[n * HDn + j] * in_proj_w[(Hn + n * HDn + j) * Hn + c];
        s_p[n][c] = acc;
    }
    __syncthreads();
    for (int e = tid; e < NHn * Dn; e += 128) { // w[n][d] = p[n] . theta[:,d]
        int n = e >> 6, d = e & (Dn - 1);
        float acc = 0.f;
#pragma unroll 8
        for (int c = 0; c < Hn; c++) acc += s_p[n][c] * theta_w[c * Dn + d];
        g_w[(b * NHn + n) * Dn + d] = acc * 0.17677669529663687f;
    }
}

// ---------------------------------------------------------------------------
// K_sc: grid (NS, B). Build xg tile from x (fused conv), 4-head scores,
// slice softmax partials (m, l), weighted-sum partials u.
// ---------------------------------------------------------------------------
__global__ void __launch_bounds__(256) score_kernel(const float* __restrict__ x)
{
    const int s = blockIdx.x, b = blockIdx.y, tid = threadIdx.x;
    const int t0 = s * SL;

    __shared__ float xg[SL][Dn + 1];     // +1 pad: conflict-free column reads
    __shared__ float sc[NHn][SL];
    __shared__ float sw[NHn][Dn];

    sw[tid >> 6][tid & 63] = g_w[b * NHn * Dn + tid];

    // fused conv: xg tile straight from x
    for (int idx = tid; idx < SL * Dn; idx += 256) {
        int d = idx & (Dn - 1), tl = idx >> 6, t = t0 + tl;
        float sum = 0.f, ws = 0.f;
#pragma unroll
        for (int dd = -3; dd <= 3; dd++) {
            int tt = t + dd;
            if (tt >= 0 && tt < Tn) {
                float wv = 1.0f / (1.0f + (float)(dd < 0 ? -dd : dd));
                ws += wv;
                sum += wv * __ldg(&x[(b * Tn + tt) * Dn + d]);
            }
        }
        xg[tl][d] = sum / ws;
    }
    __syncthreads();

    // scores: 4 heads x 128 t
    for (int e = tid; e < NHn * SL; e += 256) {
        int n = e >> 7, tl = e & (SL - 1);
        float acc = 0.f;
#pragma unroll 8
        for (int d = 0; d < Dn; d++) acc += sw[n][d] * xg[tl][d];
        sc[n][tl] = acc;
    }
    __syncthreads();

    // per-head slice softmax partials: warp n handles head n
    if (tid < NHn * 32) {
        int n = tid >> 5, lane = tid & 31;
        float m = -1e30f;
#pragma unroll
        for (int k = 0; k < 4; k++) m = fmaxf(m, sc[n][lane + 32 * k]);
#pragma unroll
        for (int off = 16; off; off >>= 1)
            m = fmaxf(m, __shfl_xor_sync(0xFFFFFFFFu, m, off));
        float l = 0.f;
#pragma unroll
        for (int k = 0; k < 4; k++) {
            float e = expf(sc[n][lane + 32 * k] - m);
            sc[n][lane + 32 * k] = e;
            l += e;
        }
#pragma unroll
        for (int off = 16; off; off >>= 1)
            l += __shfl_xor_sync(0xFFFFFFFFu, l, off);
        if (lane == 0) {
            g_m[(b * NHn + n) * NS + s] = m;
            g_l[(b * NHn + n) * NS + s] = l;
        }
    }
    __syncthreads();

    // u partial: (n,d) per thread, sum over slice
    {
        int n = tid >> 6, d = tid & (Dn - 1);
        float acc = 0.f;
#pragma unroll 4
        for (int t = 0; t < SL; t++) acc += sc[n][t] * xg[t][d];
        g_u[((b * NHn + n) * NS + s) * Dn + d] = acc;
    }
}

// ---------------------------------------------------------------------------
// K_tail: merge slice partials, then gu -> o -> out_proj -> LN -> MLP -> out
// ---------------------------------------------------------------------------
__global__ void __launch_bounds__(256) tail_kernel(
    const float* __restrict__ theta_w,
    const float* __restrict__ theta_b,
    const float* __restrict__ in_proj_w,
    const float* __restrict__ in_proj_b,
    const float* __restrict__ out_proj_w,
    const float* __restrict__ out_proj_b,
    const float* __restrict__ ln_g,
    const float* __restrict__ ln_b,
    const float* __restrict__ w1,
    const float* __restrict__ b1,
    const float* __restrict__ w2,
    const float* __restrict__ b2,
    float* __restrict__ out)
{
    const int b = blockIdx.x, tid = threadIdx.x;
    __shared__ float s_ML[NHn][2];
    __shared__ float s_u[NHn][Dn];
    __shared__ float s_gu[NHn][Hn];
    __shared__ float s_o[Hn];
    __shared__ float s_a[Hn];
    __shared__ float s_ln[Hn];
    __shared__ float s_hid[Hn];
    __shared__ float s_mv[2];

    if (tid < NHn) {
        float M = -1e30f;
#pragma unroll
        for (int s = 0; s < NS; s++) M = fmaxf(M, g_m[(b * NHn + tid) * NS + s]);
        float L = 0.f;
#pragma unroll
        for (int s = 0; s < NS; s++)
            L += g_l[(b * NHn + tid) * NS + s] *
                 expf(g_m[(b * NHn + tid) * NS + s] - M);
        s_ML[tid][0] = M;
        s_ML[tid][1] = L;
    }
    __syncthreads();
    {
        int n = tid >> 6, d = tid & (Dn - 1);
        float acc = 0.f;
#pragma unroll
        for (int s = 0; s < NS; s++)
            acc += g_u[((b * NHn + n) * NS + s) * Dn + d] *
                   expf(g_m[(b * NHn + n) * NS + s] - s_ML[n][0]);
        s_u[n][d] = acc / s_ML[n][1];
    }
    __syncthreads();
    for (int e = tid; e < NHn * Hn; e += 256) {   // gu = theta u + theta_b
        int n = e >> 7, c = e & (Hn - 1);
        float acc = theta_b[c];
#pragma unroll 8
        for (int d = 0; d < Dn; d++) acc += theta_w[c * Dn + d] * s_u[n][d];
        s_gu[n][c] = acc;
    }
    __syncthreads();
    if (tid < Hn) {                               // o = Wv gu + bv
        int n = tid >> 5;
        float acc = in_proj_b[2 * Hn + tid];
#pragma unroll 8
        for (int c = 0; c < Hn; c++)
            acc += in_proj_w[(2 * Hn + tid) * Hn + c] * s_gu[n][c];
        s_o[tid] = acc;
    }
    __syncthreads();
    if (tid < Hn) {                               // a = out_proj o
        float acc = out_proj_b[tid];
#pragma unroll 8
        for (int h = 0; h < Hn; h++) acc += out_proj_w[tid * Hn + h] * s_o[h];
        s_a[tid] = acc;
    }
    __syncthreads();
    if (tid < 32) {                               // LN stats
        float s = s_a[tid] + s_a[tid + 32] + s_a[tid + 64] + s_a[tid + 96];
#pragma unroll
        for (int off = 16; off; off >>= 1) s += __shfl_xor_sync(0xFFFFFFFFu, s, off);
        if (tid == 0) s_mv[0] = s * (1.0f / Hn);
    }
    __syncthreads();
    if (tid < 32) {
        float mu = s_mv[0], s = 0.f;
#pragma unroll
        for (int k = 0; k < 4; k++) {
            float d = s_a[tid + 32 * k] - mu;
            s += d * d;
        }
#pragma unroll
        for (int off = 16; off; off >>= 1) s += __shfl_xor_sync(0xFFFFFFFFu, s, off);
        if (tid == 0) s_mv[1] = s * (1.0f / Hn);
    }
    __syncthreads();
    if (tid < Hn) {
        float inv = rsqrtf(s_mv[1] + 1e-5f);
        s_ln[tid] = (s_a[tid] - s_mv[0]) * inv * ln_g[tid] + ln_b[tid];
    }
    __syncthreads();
    if (tid < Hn) {                               // gelu MLP hidden
        float acc = b1[tid];
#pragma unroll 8
        for (int c = 0; c < Hn; c++) acc += w1[tid * Hn + c] * s_ln[c];
        s_hid[tid] = 0.5f * acc * (1.0f + erff(acc * 0.70710678118654752f));
    }
    __syncthreads();
    if (tid < 2) {
        float acc = b2[tid];
#pragma unroll 8
        for (int h = 0; h < Hn; h++) acc += w2[tid * Hn + h] * s_hid[h];
        out[b * 2 + tid] = acc;
    }
}

// ---------------------------------------------------------------------------
extern "C" void kernel_launch(void* const* d_in, const int* in_sizes, int n_in,
                              void* d_out, int out_size) {
    const float* x          = (const float*)d_in[0];
    const float* theta_w    = (const float*)d_in[1];
    const float* theta_b    = (const float*)d_in[2];
    const float* in_proj_w  = (const float*)d_in[3];
    const float* in_proj_b  = (const float*)d_in[4];
    const float* out_proj_w = (const float*)d_in[5];
    const float* out_proj_b = (const float*)d_in[6];
    const float* lng        = (const float*)d_in[7];
    const float* lnb        = (const float*)d_in[8];
    const float* w1         = (const float*)d_in[9];
    const float* b1         = (const float*)d_in[10];
    const float* w2         = (const float*)d_in[11];
    const float* b2         = (const float*)d_in[12];
    float* out = (float*)d_out;

    pro_kernel<<<Bn, 128>>>(x, theta_w, theta_b, in_proj_w, in_proj_b);
    score_kernel<<<dim3(NS, Bn), 256>>>(x);
    tail_kernel<<<Bn, 256>>>(theta_w, theta_b, in_proj_w, in_proj_b,
                             out_proj_w, out_proj_b, lng, lnb,
                             w1, b1, w2, b2, out);
}

// round 3
// speedup vs baseline: 2.4431x; 1.8596x over previous
#include <cuda_runtime.h>
#include <math.h>

// GraphTemporalRefiner — folded-operator decomposition.
// Output depends only on a[:, -1, :], so:
//   xg = conv7(x);  w[b,n,d] = xl[b]^T W2_n[:,d] + wb[n,d]   (W2 = Qp_n^T Kp_n/sqrt(HD))
//   scores[b,n,t] = w[b,n] . xg[b,t]  (const cancels in softmax)
//   u[b,n] = softmax-weighted sum_t xg[b,t]
//   a[b]   = C . u[b] + ab            (C folds Wv, theta, out_proj)
//   LN -> gelu MLP -> out (B,2)
// All weight folding (Qp/Kp/Vp, W2, C) is batch-independent: 2 tiny precompute
// kernels. Score kernel fuses the conv and computes w locally (no prologue).

namespace {
constexpr int Bn  = 32;
constexpr int Tn  = 1024;
constexpr int Dn  = 64;
constexpr int Hn  = 128;
constexpr int NHn = 4;
constexpr int SL  = 128;
constexpr int NS  = Tn / SL;   // 8
}

__device__ float g_P[3 * Hn * Dn];        // Qp(0..127) Kp(128..255) Vp(256..383)
__device__ float g_pb[3 * Hn];            // W@theta_b + in_proj_b
__device__ float g_W2[NHn * Dn * Dn];     // (n, k, d)
__device__ float g_wb[NHn * Dn];
__device__ float g_C[Hn * NHn * Dn];      // (i, n*64+d)
__device__ float g_ab[Hn];
__device__ float g_m[Bn * NHn * NS];
__device__ float g_l[Bn * NHn * NS];
__device__ float g_u[Bn * NHn * NS * Dn];

// ---------------------------------------------------------------------------
// pre1: P = in_proj_w @ theta_w  (384x64), pb = in_proj_w @ theta_b + in_proj_b
// grid 24, block 256: 16 rows per block, smem-staged, coalesced.
// ---------------------------------------------------------------------------
__global__ void __launch_bounds__(256) pre1_kernel(
    const float* __restrict__ theta_w,
    const float* __restrict__ theta_b,
    const float* __restrict__ in_proj_w,
    const float* __restrict__ in_proj_b)
{
    const int tid = threadIdx.x, r0 = blockIdx.x * 16;
    __shared__ float th[Hn * Dn];     // 32 KB
    __shared__ float wr[16 * Hn];     // 8 KB
    __shared__ float tb[Hn];

    for (int i = tid; i < Hn * Dn; i += 256) th[i] = theta_w[i];
    for (int i = tid; i < 16 * Hn; i += 256) wr[i] = in_proj_w[r0 * Hn + i];
    if (tid < Hn) tb[tid] = theta_b[tid];
    __syncthreads();

#pragma unroll
    for (int k = 0; k < 4; k++) {
        int o = tid + k * 256;        // 16*64 outputs
        int i = o >> 6, d = o & 63;
        float acc = 0.f;
#pragma unroll 8
        for (int c = 0; c < Hn; c++) acc += wr[i * Hn + c] * th[c * Dn + d];
        g_P[(r0 + i) * Dn + d] = acc;
    }
    if (tid < 16) {
        float acc = in_proj_b[r0 + tid];
#pragma unroll 8
        for (int c = 0; c < Hn; c++) acc += wr[tid * Hn + c] * tb[c];
        g_pb[r0 + tid] = acc;
    }
}

// ---------------------------------------------------------------------------
// pre2: blocks 0..15 -> W2/wb; blocks 16..31 -> C/ab
// ---------------------------------------------------------------------------
__global__ void __launch_bounds__(256) pre2_kernel(
    const float* __restrict__ out_proj_w,
    const float* __restrict__ out_proj_b)
{
    const int tid = threadIdx.x;
    const float SCALE = 0.17677669529663687f;   // 1/sqrt(32)

    if (blockIdx.x < 16) {
        // W2[n][e][d] = sum_j Qp[n32+j,e] * Kp[n32+j,d] * SCALE
        const int n = blockIdx.x >> 2, q = blockIdx.x & 3;
        __shared__ float Qn[32 * Dn];   // 8 KB
        __shared__ float Kn[32 * Dn];
        for (int i = tid; i < 32 * Dn; i += 256) {
            Qn[i] = g_P[(n * 32) * Dn + i];
            Kn[i] = g_P[(Hn + n * 32) * Dn + i];
        }
        __syncthreads();
#pragma unroll
        for (int k = 0; k < 4; k++) {
            int o = tid + k * 256;                // 16*64 outputs
            int e = q * 16 + (o >> 6), d = o & 63;
            float acc = 0.f;
#pragma unroll 8
            for (int j = 0; j < 32; j++) acc += Qn[j * Dn + e] * Kn[j * Dn + d];
            g_W2[(n * Dn + e) * Dn + d] = acc * SCALE;
        }
        if (q == 0 && tid < Dn) {
            float acc = 0.f;
#pragma unroll 8
            for (int j = 0; j < 32; j++) acc += g_pb[n * 32 + j] * Kn[j * Dn + tid];
            g_wb[n * Dn + tid] = acc * SCALE;
        }
    } else {
        // C[i][n*64+d] = sum_j OP[i, n32+j] * Vp[n32+j, d];  ab folds biases
        const int chunk = blockIdx.x - 16;        // rows i = chunk*8..+7
        __shared__ float Vp[Hn * Dn];   // 32 KB
        __shared__ float OPs[8 * Hn];   // 4 KB
        __shared__ float vb[Hn];
        for (int i = tid; i < Hn * Dn; i += 256) Vp[i] = g_P[2 * Hn * Dn + i];
        for (int i = tid; i < 8 * Hn; i += 256) OPs[i] = out_proj_w[chunk * 8 * Hn + i];
        if (tid < Hn) vb[tid] = g_pb[2 * Hn + tid];
        __syncthreads();
#pragma unroll
        for (int k = 0; k < 8; k++) {
            int o = tid + k * 256;                // 8*256 outputs
            int il = o >> 8, nd = o & 255;
            int n = nd >> 6, d = nd & 63;
            float acc = 0.f;
#pragma unroll 8
            for (int j = 0; j < 32; j++)
                acc += OPs[il * Hn + n * 32 + j] * Vp[(n * 32 + j) * Dn + d];
            g_C[(chunk * 8 + il) * (NHn * Dn) + nd] = acc;
        }
        if (tid < 8) {
            float acc = out_proj_b[chunk * 8 + tid];
#pragma unroll 8
            for (int h = 0; h < Hn; h++) acc += OPs[tid * Hn + h] * vb[h];
            g_ab[chunk * 8 + tid] = acc;
        }
    }
}

// ---------------------------------------------------------------------------
// score: grid (NS, B). Fused conv -> xg tile; local w from W2; 4-head scores;
// slice softmax partials; weighted xg sums.
// ---------------------------------------------------------------------------
__global__ void __launch_bounds__(256) score_kernel(const float* __restrict__ x)
{
    const int s = blockIdx.x, b = blockIdx.y, tid = threadIdx.x;
    const int t0 = s * SL;

    __shared__ float xg[SL][Dn + 1];   // 33.3 KB
    __shared__ float sc[NHn][SL];
    __shared__ float sw[NHn][Dn];
    __shared__ float sxl[Dn];

    // xl[b]: conv at t = T-1 (forward taps OOB)
    if (tid < Dn) {
        float sum = 0.f, ws = 0.f;
#pragma unroll
        for (int dd = 0; dd < 4; dd++) {
            float wv = 1.0f / (1.0f + (float)dd);
            ws += wv;
            sum += wv * __ldg(&x[(b * Tn + (Tn - 1 - dd)) * Dn + tid]);
        }
        sxl[tid] = sum / ws;
    }

    // fused conv xg tile
    for (int idx = tid; idx < SL * Dn; idx += 256) {
        int d = idx & 63, tl = idx >> 6, t = t0 + tl;
        float sum = 0.f, ws = 0.f;
#pragma unroll
        for (int dd = -3; dd <= 3; dd++) {
            int tt = t + dd;
            if (tt >= 0 && tt < Tn) {
                float wv = 1.0f / (1.0f + (float)(dd < 0 ? -dd : dd));
                ws += wv;
                sum += wv * __ldg(&x[(b * Tn + tt) * Dn + d]);
            }
        }
        xg[tl][d] = sum / ws;
    }
    __syncthreads();

    // w[n][d] = wb[n][d] + sum_k xl[k] * W2[n][k][d]  (coalesced over d)
    {
        int n = tid >> 6, d = tid & 63;
        float acc = g_wb[tid];
#pragma unroll 8
        for (int k = 0; k < Dn; k++)
            acc += sxl[k] * __ldg(&g_W2[(n * Dn + k) * Dn + d]);
        sw[n][d] = acc;
    }
    __syncthreads();

    // scores
    for (int e = tid; e < NHn * SL; e += 256) {
        int n = e >> 7, tl = e & (SL - 1);
        float acc = 0.f;
#pragma unroll 8
        for (int d = 0; d < Dn; d++) acc += sw[n][d] * xg[tl][d];
        sc[n][tl] = acc;
    }
    __syncthreads();

    // per-head slice softmax partials (warp n = head n)
    if (tid < NHn * 32) {
        int n = tid >> 5, lane = tid & 31;
        float m = -1e30f;
#pragma unroll
        for (int k = 0; k < 4; k++) m = fmaxf(m, sc[n][lane + 32 * k]);
#pragma unroll
        for (int off = 16; off; off >>= 1)
            m = fmaxf(m, __shfl_xor_sync(0xFFFFFFFFu, m, off));
        float l = 0.f;
#pragma unroll
        for (int k = 0; k < 4; k++) {
            float e = expf(sc[n][lane + 32 * k] - m);
            sc[n][lane + 32 * k] = e;
            l += e;
        }
#pragma unroll
        for (int off = 16; off; off >>= 1)
            l += __shfl_xor_sync(0xFFFFFFFFu, l, off);
        if (lane == 0) {
            g_m[(b * NHn + n) * NS + s] = m;
            g_l[(b * NHn + n) * NS + s] = l;
        }
    }
    __syncthreads();

    // u partial
    {
        int n = tid >> 6, d = tid & 63;
        float acc = 0.f;
#pragma unroll 4
        for (int t = 0; t < SL; t++) acc += sc[n][t] * xg[t][d];
        g_u[((b * NHn + n) * NS + s) * Dn + d] = acc;
    }
}

// ---------------------------------------------------------------------------
// tail: merge partials -> u; a = C u + ab (warp-dots); LN; gelu MLP -> out
// ---------------------------------------------------------------------------
__global__ void __launch_bounds__(256) tail_kernel(
    const float* __restrict__ ln_g,
    const float* __restrict__ ln_b,
    const float* __restrict__ w1,
    const float* __restrict__ b1,
    const float* __restrict__ w2,
    const float* __restrict__ b2,
    float* __restrict__ out)
{
    const int b = blockIdx.x, tid = threadIdx.x;
    const int warp = tid >> 5, lane = tid & 31;

    __shared__ float s_ML[NHn][2];
    __shared__ float s_u[NHn * Dn];
    __shared__ float s_a[Hn];
    __shared__ float s_ln[Hn];
    __shared__ float s_hid[Hn];
    __shared__ float s_mv[2];

    if (tid < NHn) {
        float M = -1e30f;
#pragma unroll
        for (int s = 0; s < NS; s++) M = fmaxf(M, g_m[(b * NHn + tid) * NS + s]);
        float L = 0.f;
#pragma unroll
        for (int s = 0; s < NS; s++)
            L += g_l[(b * NHn + tid) * NS + s] *
                 expf(g_m[(b * NHn + tid) * NS + s] - M);
        s_ML[tid][0] = M;
        s_ML[tid][1] = L;
    }
    __syncthreads();
    {
        int n = tid >> 6, d = tid & 63;
        float acc = 0.f;
#pragma unroll
        for (int s = 0; s < NS; s++)
            acc += g_u[((b * NHn + n) * NS + s) * Dn + d] *
                   expf(g_m[(b * NHn + n) * NS + s] - s_ML[n][0]);
        s_u[n * Dn + d] = acc / s_ML[n][1];
    }
    __syncthreads();

    // a[i] = ab[i] + C[i][:] . u   — warp per output, coalesced
#pragma unroll
    for (int k = 0; k < 16; k++) {
        int i = warp + 8 * k;
        float acc = 0.f;
#pragma unroll
        for (int m = 0; m < 8; m++)
            acc += __ldg(&g_C[i * 256 + lane + 32 * m]) * s_u[lane + 32 * m];
#pragma unroll
        for (int off = 16; off; off >>= 1) acc += __shfl_xor_sync(0xFFFFFFFFu, acc, off);
        if (lane == 0) s_a[i] = acc + g_ab[i];
    }
    __syncthreads();

    // LayerNorm over 128
    if (tid < 32) {
        float s = s_a[tid] + s_a[tid + 32] + s_a[tid + 64] + s_a[tid + 96];
#pragma unroll
        for (int off = 16; off; off >>= 1) s += __shfl_xor_sync(0xFFFFFFFFu, s, off);
        if (tid == 0) s_mv[0] = s * (1.0f / Hn);
    }
    __syncthreads();
    if (tid < 32) {
        float mu = s_mv[0], s = 0.f;
#pragma unroll
        for (int k = 0; k < 4; k++) {
            float d = s_a[tid + 32 * k] - mu;
            s += d * d;
        }
#pragma unroll
        for (int off = 16; off; off >>= 1) s += __shfl_xor_sync(0xFFFFFFFFu, s, off);
        if (tid == 0) s_mv[1] = s * (1.0f / Hn);
    }
    __syncthreads();
    if (tid < Hn) {
        float inv = rsqrtf(s_mv[1] + 1e-5f);
        s_ln[tid] = (s_a[tid] - s_mv[0]) * inv * ln_g[tid] + ln_b[tid];
    }
    __syncthreads();

    // hid = gelu(w1 @ ln + b1) — warp per output
#pragma unroll
    for (int k = 0; k < 16; k++) {
        int i = warp + 8 * k;
        float acc = 0.f;
#pragma unroll
        for (int m = 0; m < 4; m++)
            acc += __ldg(&w1[i * Hn + lane + 32 * m]) * s_ln[lane + 32 * m];
#pragma unroll
        for (int off = 16; off; off >>= 1) acc += __shfl_xor_sync(0xFFFFFFFFu, acc, off);
        if (lane == 0) {
            float v = acc + b1[i];
            s_hid[i] = 0.5f * v * (1.0f + erff(v * 0.70710678118654752f));
        }
    }
    __syncthreads();

    if (warp < 2) {
        float acc = 0.f;
#pragma unroll
        for (int m = 0; m < 4; m++)
            acc += __ldg(&w2[warp * Hn + lane + 32 * m]) * s_hid[lane + 32 * m];
#pragma unroll
        for (int off = 16; off; off >>= 1) acc += __shfl_xor_sync(0xFFFFFFFFu, acc, off);
        if (lane == 0) out[b * 2 + warp] = acc + b2[warp];
    }
}

// ---------------------------------------------------------------------------
extern "C" void kernel_launch(void* const* d_in, const int* in_sizes, int n_in,
                              void* d_out, int out_size) {
    const float* x          = (const float*)d_in[0];
    const float* theta_w    = (const float*)d_in[1];
    const float* theta_b    = (const float*)d_in[2];
    const float* in_proj_w  = (const float*)d_in[3];
    const float* in_proj_b  = (const float*)d_in[4];
    const float* out_proj_w = (const float*)d_in[5];
    const float* out_proj_b = (const float*)d_in[6];
    const float* lng        = (const float*)d_in[7];
    const float* lnb        = (const float*)d_in[8];
    const float* w1         = (const float*)d_in[9];
    const float* b1         = (const float*)d_in[10];
    const float* w2         = (const float*)d_in[11];
    const float* b2         = (const float*)d_in[12];
    float* out = (float*)d_out;

    pre1_kernel<<<24, 256>>>(theta_w, theta_b, in_proj_w, in_proj_b);
    pre2_kernel<<<32, 256>>>(out_proj_w, out_proj_b);
    score_kernel<<<dim3(NS, Bn), 256>>>(x);
    tail_kernel<<<Bn, 256>>>(lng, lnb, w1, b1, w2, b2, out);
}